// round 6
// baseline (speedup 1.0000x reference)
#include <cuda_runtime.h>

#define Bv 32
#define Tv 1000
#define DINv 64
#define Hv 1024

#define NBG 4
#define NJG 32
#define BTILE 8
#define JTILE 32
#define NTHREADS 512
#define NW 16                // warps = k-slices
#define KPW 64               // k per warp
#define GRID (NBG * NJG)     // 128 CTAs, 1/SM

__device__ unsigned int g_bar[4 * 64];           // per-group counters, 256B apart
__device__ float2 h_bufT[2][NBG][Hv][BTILE];     // transposed + duplicated h state

struct Smem {
    float  Ws[Hv * 32];          // 131072 B : W slice [k][j], 128B rows
    float2 hd[Hv * BTILE];       //  65536 B : h(t-1) [k][b] = (v,v) pairs
    float  red[NW][BTILE][36];   //  18432 B : k-slice partials
};
// total = 215040 B < 227 KB

// ---------------------------------------------------------------------------
// Phase 1: u_in = x @ W_in^T + b -> out ; resets step counters.
// ---------------------------------------------------------------------------
__global__ void __launch_bounds__(256)
esn_uin_kernel(const float* __restrict__ x, const float* __restrict__ Wiw,
               const float* __restrict__ Wib, float* __restrict__ out)
{
    if (blockIdx.x == 0 && threadIdx.x < 4) g_bar[threadIdx.x * 64] = 0u;

    __shared__ float2 xs2[DINv * 18];
    __shared__ float  wis[DINv * 130];

    const int tid = threadIdx.x;
    const int R0  = blockIdx.x * 16;

    {
        const int kk = tid & 63, r4 = tid >> 6;
        #pragma unroll
        for (int i = 0; i < 4; ++i) {
            int r = r4 * 4 + i;
            float v = x[(size_t)(R0 + r) * DINv + kk];
            xs2[kk * 18 + r] = make_float2(v, v);
        }
    }

    const int jp = tid & 63;
    const int rq = tid >> 6;
    const unsigned wis_s = (unsigned)__cvta_generic_to_shared(wis);
    const unsigned xs_s  = (unsigned)__cvta_generic_to_shared(xs2);

    for (int jc = 0; jc < 8; ++jc) {
        __syncthreads();
        for (int idx = tid; idx < 128 * DINv; idx += 256) {
            int jj = idx >> 6, kk = idx & 63;
            wis[kk * 130 + jj] = Wiw[(jc * 128 + jj) * DINv + kk];
        }
        __syncthreads();

        float2 bias2 = *(const float2*)&Wib[jc * 128 + 2 * jp];
        unsigned long long acc[4], b2;
        asm("mov.b64 %0,{%1,%2};" : "=l"(b2) : "f"(bias2.x), "f"(bias2.y));
        #pragma unroll
        for (int r = 0; r < 4; ++r) acc[r] = b2;

        unsigned wa = wis_s + (2 * jp) * 4;
        unsigned xa = xs_s + (rq * 4) * 8;
        #pragma unroll 8
        for (int k = 0; k < DINv; ++k) {
            unsigned long long w01, x0, x1, x2, x3;
            asm("ld.shared.u64 %0,[%1];" : "=l"(w01) : "r"(wa));
            asm("ld.shared.u64 %0,[%1];" : "=l"(x0) : "r"(xa));
            asm("ld.shared.u64 %0,[%1+8];" : "=l"(x1) : "r"(xa));
            asm("ld.shared.u64 %0,[%1+16];" : "=l"(x2) : "r"(xa));
            asm("ld.shared.u64 %0,[%1+24];" : "=l"(x3) : "r"(xa));
            asm("fma.rn.f32x2 %0,%1,%2,%0;" : "+l"(acc[0]) : "l"(w01), "l"(x0));
            asm("fma.rn.f32x2 %0,%1,%2,%0;" : "+l"(acc[1]) : "l"(w01), "l"(x1));
            asm("fma.rn.f32x2 %0,%1,%2,%0;" : "+l"(acc[2]) : "l"(w01), "l"(x2));
            asm("fma.rn.f32x2 %0,%1,%2,%0;" : "+l"(acc[3]) : "l"(w01), "l"(x3));
            wa += 130 * 4;
            xa += 18 * 8;
        }

        #pragma unroll
        for (int r = 0; r < 4; ++r) {
            float fx, fy;
            asm("mov.b64 {%0,%1},%2;" : "=f"(fx), "=f"(fy) : "l"(acc[r]));
            float2* op = (float2*)&out[(size_t)(R0 + rq * 4 + r) * Hv + jc * 128 + 2 * jp];
            *op = make_float2(fx, fy);
        }
    }
}

// ---------------------------------------------------------------------------
// Phase 2: persistent scan. 512 threads; warp = 64-k slice;
// thread = 4j x 2b register block. h kept transposed+duplicated in global.
// ---------------------------------------------------------------------------
__global__ void __launch_bounds__(NTHREADS, 1)
esn_scan_kernel(const float* __restrict__ W, float* __restrict__ out)
{
    extern __shared__ unsigned char smem_raw[];
    Smem& sm = *reinterpret_cast<Smem*>(smem_raw);

    const int tid  = threadIdx.x;
    const int lane = tid & 31;
    const int wid  = tid >> 5;          // k-slice 0..15
    const int jt   = lane >> 2;         // j-quad: j = 4*jt .. 4*jt+3
    const int bp   = lane & 3;          // b-pair: b = 2*bp, 2*bp+1
    const int grp  = blockIdx.x & (NBG - 1);
    const int jg   = blockIdx.x >> 2;
    const int b0   = grp * BTILE;
    const int j0   = jg * JTILE;
    unsigned* bar  = &g_bar[grp * 64];

    // epilogue mapping (tid < 256): b = eb, j = j0 + ej
    const int eb = tid >> 5;            // 0..7 (valid when tid < 256)
    const int ej = lane;

    // one-time W slice: Ws[k*32 + jl] = W[j0+jl][k]  (conflict-free STS)
    {
        const int jl = tid & 31;
        for (int k = tid >> 5; k < Hv; k += NW)
            sm.Ws[k * 32 + jl] = W[(size_t)(j0 + jl) * Hv + k];
    }

    const unsigned ws_s = (unsigned)__cvta_generic_to_shared(sm.Ws)
                          + (wid * KPW * 32 + jt * 4) * 4;
    const unsigned hd_s = (unsigned)__cvta_generic_to_shared(sm.hd)
                          + (wid * KPW * BTILE + bp * 2) * 8;

    __syncthreads();

    const float lr  = 0.9f;
    const float olr = 1.0f - lr;
    float hprev = 0.0f;                 // own (eb, j0+ej) state, kept in register

    for (int t = 0; t < Tv; ++t) {
        // prefetch u_in (independent of h)
        float u0 = 0.0f;
        if (tid < 256)
            u0 = out[((size_t)(b0 + eb) * Tv + t) * Hv + j0 + ej];

        if (t > 0) {
            // group barrier: all 32 CTAs of this batch group finished t-1
            if (tid == 0) {
                const unsigned tgt = (unsigned)t * NJG;
                unsigned v;
                do {
                    asm volatile("ld.acquire.gpu.global.u32 %0, [%1];"
                                 : "=r"(v) : "l"(bar));
                } while (v < tgt);
            }
        }
        __syncthreads();

        float ssum = 0.0f;

        if (t > 0) {
            // gather: linear coalesced copy h_bufT[tp][grp] (64KB) -> sm.hd
            {
                const float4* src =
                    (const float4*)&h_bufT[(t - 1) & 1][grp][0][0];
                float4* dst = (float4*)sm.hd;
                #pragma unroll
                for (int i = 0; i < 8; ++i) {
                    int idx = tid + i * NTHREADS;
                    dst[idx] = __ldcg(src + idx);
                }
            }
        }
        __syncthreads();

        if (t > 0) {
            // GEMM: per k = 1 LDS.128 (W quad) + 1 LDS.128 (dup h pair) + 4 FFMA2
            unsigned long long a00 = 0ull, a01 = 0ull, a10 = 0ull, a11 = 0ull;
            {
                unsigned wa = ws_s, ha = hd_s;
                #pragma unroll 2
                for (int i = 0; i < 4; ++i) {
                    #pragma unroll
                    for (int u = 0; u < 16; ++u) {
                        unsigned long long w01, w23, h00, h11;
                        asm("ld.shared.v2.u64 {%0,%1},[%2];"
                            : "=l"(w01), "=l"(w23) : "r"(wa + u * 128));
                        asm("ld.shared.v2.u64 {%0,%1},[%2];"
                            : "=l"(h00), "=l"(h11) : "r"(ha + u * 64));
                        asm("fma.rn.f32x2 %0,%1,%2,%0;" : "+l"(a00) : "l"(w01), "l"(h00));
                        asm("fma.rn.f32x2 %0,%1,%2,%0;" : "+l"(a01) : "l"(w23), "l"(h00));
                        asm("fma.rn.f32x2 %0,%1,%2,%0;" : "+l"(a10) : "l"(w01), "l"(h11));
                        asm("fma.rn.f32x2 %0,%1,%2,%0;" : "+l"(a11) : "l"(w23), "l"(h11));
                    }
                    wa += 16 * 128;
                    ha += 16 * 64;
                }
            }

            // partials: red[wid][b][jt*4..+3] as float4
            {
                float x0, y0, x1, y1;
                asm("mov.b64 {%0,%1},%2;" : "=f"(x0), "=f"(y0) : "l"(a00));
                asm("mov.b64 {%0,%1},%2;" : "=f"(x1), "=f"(y1) : "l"(a01));
                *(float4*)&sm.red[wid][2 * bp][jt * 4] = make_float4(x0, y0, x1, y1);
                asm("mov.b64 {%0,%1},%2;" : "=f"(x0), "=f"(y0) : "l"(a10));
                asm("mov.b64 {%0,%1},%2;" : "=f"(x1), "=f"(y1) : "l"(a11));
                *(float4*)&sm.red[wid][2 * bp + 1][jt * 4] = make_float4(x0, y0, x1, y1);
            }
        }
        __syncthreads();

        if (t > 0 && tid < 256) {
            // reduce 16 k-slices for output (b=eb, j=ej): consecutive lanes, 1 wf/s
            #pragma unroll
            for (int s = 0; s < NW; ++s)
                ssum += sm.red[s][eb][ej];
        }

        if (tid < 256) {
            const float u    = u0 + ssum;
            const float hnew = olr * hprev + lr * tanhf(u);
            hprev = hnew;

            out[((size_t)(b0 + eb) * Tv + t) * Hv + j0 + ej] = hnew;
            // publish transposed + duplicated for next step's gather
            h_bufT[t & 1][grp][j0 + ej][eb] = make_float2(hnew, hnew);
        }

        __syncthreads();                // CTA's h_bufT stores done
        if (tid == 0)
            asm volatile("red.release.gpu.global.add.u32 [%0], 1;" :: "l"(bar));
    }
}

extern "C" void kernel_launch(void* const* d_in, const int* in_sizes, int n_in,
                              void* d_out, int out_size)
{
    const float* x   = (const float*)d_in[0];  // [32,1000,64]
    const float* Wiw = (const float*)d_in[1];  // [1024,64]
    const float* Wib = (const float*)d_in[2];  // [1024]
    const float* W   = (const float*)d_in[3];  // [1024,1024]
    float* out = (float*)d_out;                // [32,1000,1024]

    const size_t smem = sizeof(Smem);
    cudaFuncSetAttribute(esn_scan_kernel,
                         cudaFuncAttributeMaxDynamicSharedMemorySize, (int)smem);

    esn_uin_kernel<<<(Bv * Tv) / 16, 256>>>(x, Wiw, Wib, out);
    esn_scan_kernel<<<GRID, NTHREADS, smem>>>(W, out);
}

// round 7
// speedup vs baseline: 1.4171x; 1.4171x over previous
#include <cuda_runtime.h>

#define Bv 32
#define Tv 1000
#define DINv 64
#define Hv 1024

#define NBG 4
#define NJG 32
#define BTILE 8
#define JTILE 32
#define NTHREADS 256
#define GRID (NBG * NJG)     // 128 CTAs, 1/SM

#define WS 36                // W row stride (floats): 144B, 16B-aligned
#define HS 10                // h row stride (floats): 40B, LDS.64-aligned, bank-spread
#define RS 274               // red k-slice stride (floats)
#define NKS 64               // k-slices
#define KPT 16               // k per thread (strided by 64)

__device__ unsigned int g_bar[4 * 64];          // per-group counters, 256B apart
__device__ float h_bufT[2][NBG][Hv * HS];       // h state, pre-laid-out [k*10+b]

struct Smem {
    float Ws[Hv * WS];                  // 147456 B
    union {
        float h_s[Hv * HS];             // 40960 B (live: gather -> end of GEMM)
        float red[NKS * RS];            // 70144 B (live: after GEMM -> reduce read)
    } u;
};
// total = 217600 B < 227 KB

// ---------------------------------------------------------------------------
// Phase 1: u_in = x @ W_in^T + b -> out ; resets step counters.
// ---------------------------------------------------------------------------
__global__ void __launch_bounds__(256)
esn_uin_kernel(const float* __restrict__ x, const float* __restrict__ Wiw,
               const float* __restrict__ Wib, float* __restrict__ out)
{
    if (blockIdx.x == 0 && threadIdx.x < 4) g_bar[threadIdx.x * 64] = 0u;

    __shared__ float2 xs2[DINv * 18];
    __shared__ float  wis[DINv * 130];

    const int tid = threadIdx.x;
    const int R0  = blockIdx.x * 16;

    {
        const int kk = tid & 63, r4 = tid >> 6;
        #pragma unroll
        for (int i = 0; i < 4; ++i) {
            int r = r4 * 4 + i;
            float v = x[(size_t)(R0 + r) * DINv + kk];
            xs2[kk * 18 + r] = make_float2(v, v);
        }
    }

    const int jp = tid & 63;
    const int rq = tid >> 6;
    const unsigned wis_s = (unsigned)__cvta_generic_to_shared(wis);
    const unsigned xs_s  = (unsigned)__cvta_generic_to_shared(xs2);

    for (int jc = 0; jc < 8; ++jc) {
        __syncthreads();
        for (int idx = tid; idx < 128 * DINv; idx += 256) {
            int jj = idx >> 6, kk = idx & 63;
            wis[kk * 130 + jj] = Wiw[(jc * 128 + jj) * DINv + kk];
        }
        __syncthreads();

        float2 bias2 = *(const float2*)&Wib[jc * 128 + 2 * jp];
        unsigned long long acc[4], b2;
        asm("mov.b64 %0,{%1,%2};" : "=l"(b2) : "f"(bias2.x), "f"(bias2.y));
        #pragma unroll
        for (int r = 0; r < 4; ++r) acc[r] = b2;

        unsigned wa = wis_s + (2 * jp) * 4;
        unsigned xa = xs_s + (rq * 4) * 8;
        #pragma unroll 8
        for (int k = 0; k < DINv; ++k) {
            unsigned long long w01, x0, x1, x2, x3;
            asm("ld.shared.u64 %0,[%1];" : "=l"(w01) : "r"(wa));
            asm("ld.shared.u64 %0,[%1];" : "=l"(x0) : "r"(xa));
            asm("ld.shared.u64 %0,[%1+8];" : "=l"(x1) : "r"(xa));
            asm("ld.shared.u64 %0,[%1+16];" : "=l"(x2) : "r"(xa));
            asm("ld.shared.u64 %0,[%1+24];" : "=l"(x3) : "r"(xa));
            asm("fma.rn.f32x2 %0,%1,%2,%0;" : "+l"(acc[0]) : "l"(w01), "l"(x0));
            asm("fma.rn.f32x2 %0,%1,%2,%0;" : "+l"(acc[1]) : "l"(w01), "l"(x1));
            asm("fma.rn.f32x2 %0,%1,%2,%0;" : "+l"(acc[2]) : "l"(w01), "l"(x2));
            asm("fma.rn.f32x2 %0,%1,%2,%0;" : "+l"(acc[3]) : "l"(w01), "l"(x3));
            wa += 130 * 4;
            xa += 18 * 8;
        }

        #pragma unroll
        for (int r = 0; r < 4; ++r) {
            float fx, fy;
            asm("mov.b64 {%0,%1},%2;" : "=f"(fx), "=f"(fy) : "l"(acc[r]));
            float2* op = (float2*)&out[(size_t)(R0 + rq * 4 + r) * Hv + jc * 128 + 2 * jp];
            *op = make_float2(fx, fy);
        }
    }
}

// ---------------------------------------------------------------------------
// Phase 2: persistent scan. 256 threads; thread = 8j x 8b block over 16
// strided k (1 B/MAC crossbar). h published pre-laid-out; hprev in register.
// ---------------------------------------------------------------------------
__global__ void __launch_bounds__(NTHREADS, 1)
esn_scan_kernel(const float* __restrict__ W, float* __restrict__ out)
{
    extern __shared__ unsigned char smem_raw[];
    Smem& sm = *reinterpret_cast<Smem*>(smem_raw);

    const int tid  = threadIdx.x;
    const int lane = tid & 31;
    const int jt   = tid & 3;           // j-octet: j = jt*8 .. jt*8+7
    const int ks   = tid >> 2;          // k-slice 0..63 (k = ks + 64*i)
    const int grp  = blockIdx.x & (NBG - 1);
    const int jg   = blockIdx.x >> 2;
    const int b0   = grp * BTILE;
    const int j0   = jg * JTILE;
    unsigned* bar  = &g_bar[grp * 64];

    // epilogue mapping: b = eb, j = j0 + ej
    const int eb = tid >> 5;            // 0..7
    const int ej = lane;

    // one-time W slice: Ws[k*36 + jl] = W[j0+jl][k]
    {
        const int jl = tid & 31;
        for (int k4 = tid >> 5; k4 < Hv / 4; k4 += 8) {
            float4 v = *(const float4*)&W[(size_t)(j0 + jl) * Hv + k4 * 4];
            sm.Ws[(k4 * 4 + 0) * WS + jl] = v.x;
            sm.Ws[(k4 * 4 + 1) * WS + jl] = v.y;
            sm.Ws[(k4 * 4 + 2) * WS + jl] = v.z;
            sm.Ws[(k4 * 4 + 3) * WS + jl] = v.w;
        }
    }

    const unsigned ws_s = (unsigned)__cvta_generic_to_shared(sm.Ws)
                          + (ks * WS + jt * 8) * 4;
    const unsigned hs_s = (unsigned)__cvta_generic_to_shared(sm.u.h_s)
                          + (ks * HS) * 4;

    __syncthreads();

    const float lr  = 0.9f;
    const float olr = 1.0f - lr;
    float hprev = 0.0f;                 // own (eb, j0+ej) state in register

    for (int t = 0; t < Tv; ++t) {
        // prefetch u_in (independent of h; consumed after GEMM)
        const float u0 = out[((size_t)(b0 + eb) * Tv + t) * Hv + j0 + ej];

        float ssum = 0.0f;

        if (t > 0) {
            // group barrier: all 32 CTAs of this batch group finished t-1
            if (tid == 0) {
                const unsigned tgt = (unsigned)t * NJG;
                unsigned v;
                do {
                    asm volatile("ld.acquire.gpu.global.u32 %0, [%1];"
                                 : "=r"(v) : "l"(bar));
                } while (v < tgt);
            }
        }
        __syncthreads();   // (A) barrier done; prior-step red reads complete

        if (t > 0) {
            // gather: pure linear copy, 40KB, LDG.128 -> STS.128 conflict-free
            const float4* src = (const float4*)&h_bufT[(t - 1) & 1][grp][0];
            float4* dst = (float4*)sm.u.h_s;
            #pragma unroll
            for (int i = 0; i < 10; ++i) {
                int idx = tid + i * NTHREADS;
                dst[idx] = __ldcg(src + idx);
            }
        }
        __syncthreads();   // (B) h_s ready

        if (t > 0) {
            // GEMM: per k = 2 LDS.128 (8 W) + 4 LDS.64 (8 h) + 8 dup + 32 FFMA2
            unsigned long long a[4][8];
            #pragma unroll
            for (int q = 0; q < 4; ++q)
                #pragma unroll
                for (int b = 0; b < 8; ++b) a[q][b] = 0ull;

            unsigned wa = ws_s, ha = hs_s;
            #pragma unroll
            for (int i = 0; i < KPT; ++i) {
                unsigned long long w01, w23, w45, w67;
                float h0, h1, h2, h3, h4, h5, h6, h7;
                asm("ld.shared.v2.u64 {%0,%1},[%2];"
                    : "=l"(w01), "=l"(w23) : "r"(wa));
                asm("ld.shared.v2.u64 {%0,%1},[%2+16];"
                    : "=l"(w45), "=l"(w67) : "r"(wa));
                asm("ld.shared.v2.f32 {%0,%1},[%2];"    : "=f"(h0), "=f"(h1) : "r"(ha));
                asm("ld.shared.v2.f32 {%0,%1},[%2+8];"  : "=f"(h2), "=f"(h3) : "r"(ha));
                asm("ld.shared.v2.f32 {%0,%1},[%2+16];" : "=f"(h4), "=f"(h5) : "r"(ha));
                asm("ld.shared.v2.f32 {%0,%1},[%2+24];" : "=f"(h6), "=f"(h7) : "r"(ha));
                float hv[8] = {h0, h1, h2, h3, h4, h5, h6, h7};
                #pragma unroll
                for (int b = 0; b < 8; ++b) {
                    unsigned long long hd;
                    asm("mov.b64 %0,{%1,%1};" : "=l"(hd) : "f"(hv[b]));
                    asm("fma.rn.f32x2 %0,%1,%2,%0;" : "+l"(a[0][b]) : "l"(w01), "l"(hd));
                    asm("fma.rn.f32x2 %0,%1,%2,%0;" : "+l"(a[1][b]) : "l"(w23), "l"(hd));
                    asm("fma.rn.f32x2 %0,%1,%2,%0;" : "+l"(a[2][b]) : "l"(w45), "l"(hd));
                    asm("fma.rn.f32x2 %0,%1,%2,%0;" : "+l"(a[3][b]) : "l"(w67), "l"(hd));
                }
                wa += 64 * WS * 4;
                ha += 64 * HS * 4;
            }

            __syncthreads();   // (C) h_s reads done before red overwrite (union)

            // k-slice partials: red[ks][b*34 + j..] as float2 pairs
            #pragma unroll
            for (int b = 0; b < 8; ++b) {
                #pragma unroll
                for (int q = 0; q < 4; ++q) {
                    float fx, fy;
                    asm("mov.b64 {%0,%1},%2;" : "=f"(fx), "=f"(fy) : "l"(a[q][b]));
                    *(float2*)&sm.u.red[ks * RS + b * 34 + jt * 8 + q * 2] =
                        make_float2(fx, fy);
                }
            }
        } else {
            __syncthreads();   // (C) keep sync count uniform
        }
        __syncthreads();       // (D) red ready

        if (t > 0) {
            const float* rp = &sm.u.red[eb * 34 + ej];
            #pragma unroll 16
            for (int s = 0; s < NKS; ++s) ssum += rp[s * RS];
        }

        // epilogue: h_new = 0.1*h + 0.9*tanh(u_in + h@W^T)
        const float u    = u0 + ssum;
        const float hnew = olr * hprev + lr * tanhf(u);
        hprev = hnew;

        out[((size_t)(b0 + eb) * Tv + t) * Hv + j0 + ej] = hnew;
        // publish directly in the SMEM image layout for next step's linear copy
        h_bufT[t & 1][grp][(j0 + ej) * HS + eb] = hnew;

        __syncthreads();       // (E) publish + red reads done
        if (tid == 0)
            asm volatile("red.release.gpu.global.add.u32 [%0], 1;" :: "l"(bar));
    }
}

extern "C" void kernel_launch(void* const* d_in, const int* in_sizes, int n_in,
                              void* d_out, int out_size)
{
    const float* x   = (const float*)d_in[0];  // [32,1000,64]
    const float* Wiw = (const float*)d_in[1];  // [1024,64]
    const float* Wib = (const float*)d_in[2];  // [1024]
    const float* W   = (const float*)d_in[3];  // [1024,1024]
    float* out = (float*)d_out;                // [32,1000,1024]

    const size_t smem = sizeof(Smem);
    cudaFuncSetAttribute(esn_scan_kernel,
                         cudaFuncAttributeMaxDynamicSharedMemorySize, (int)smem);

    esn_uin_kernel<<<(Bv * Tv) / 16, 256>>>(x, Wiw, Wib, out);
    esn_scan_kernel<<<GRID, NTHREADS, smem>>>(W, out);
}

// round 8
// speedup vs baseline: 1.4536x; 1.0257x over previous
#include <cuda_runtime.h>

#define Bv 32
#define Tv 1000
#define DINv 64
#define Hv 1024

#define NBG 4
#define NJG 32
#define BTILE 8
#define JTILE 32
#define NTHREADS 256
#define GRID (NBG * NJG)     // 128 CTAs, 1/SM

#define WS 36                // W row stride (floats)
#define HS 10                // h row stride (floats)
#define RS 296               // red k-slice stride (floats): 1184B = 9*128+32 -> 4-wf STS.128
#define NKS 64               // k-slices
#define KPT 16               // k per thread (strided by 64)

__device__ unsigned int g_bar[4 * 64];          // per-group counters, 256B apart
__device__ float h_bufT[2][NBG][Hv * HS];       // h state, pre-laid-out [k*10+b]

struct Smem {
    float Ws[Hv * WS];                  // 147456 B
    union {
        float h_s[Hv * HS];             // 40960 B (live: gather -> end of GEMM)
        float red[NKS * RS];            // 75776 B (live: after GEMM -> reduce read)
    } u;
};
// total = 223232 B < 232448 B

// ---------------------------------------------------------------------------
// Phase 1: u_in = x @ W_in^T + b -> out ; resets step counters.
// ---------------------------------------------------------------------------
__global__ void __launch_bounds__(256)
esn_uin_kernel(const float* __restrict__ x, const float* __restrict__ Wiw,
               const float* __restrict__ Wib, float* __restrict__ out)
{
    if (blockIdx.x == 0 && threadIdx.x < 4) g_bar[threadIdx.x * 64] = 0u;

    __shared__ float2 xs2[DINv * 18];
    __shared__ float  wis[DINv * 130];

    const int tid = threadIdx.x;
    const int R0  = blockIdx.x * 16;

    {
        const int kk = tid & 63, r4 = tid >> 6;
        #pragma unroll
        for (int i = 0; i < 4; ++i) {
            int r = r4 * 4 + i;
            float v = x[(size_t)(R0 + r) * DINv + kk];
            xs2[kk * 18 + r] = make_float2(v, v);
        }
    }

    const int jp = tid & 63;
    const int rq = tid >> 6;
    const unsigned wis_s = (unsigned)__cvta_generic_to_shared(wis);
    const unsigned xs_s  = (unsigned)__cvta_generic_to_shared(xs2);

    for (int jc = 0; jc < 8; ++jc) {
        __syncthreads();
        for (int idx = tid; idx < 128 * DINv; idx += 256) {
            int jj = idx >> 6, kk = idx & 63;
            wis[kk * 130 + jj] = Wiw[(jc * 128 + jj) * DINv + kk];
        }
        __syncthreads();

        float2 bias2 = *(const float2*)&Wib[jc * 128 + 2 * jp];
        unsigned long long acc[4], b2;
        asm("mov.b64 %0,{%1,%2};" : "=l"(b2) : "f"(bias2.x), "f"(bias2.y));
        #pragma unroll
        for (int r = 0; r < 4; ++r) acc[r] = b2;

        unsigned wa = wis_s + (2 * jp) * 4;
        unsigned xa = xs_s + (rq * 4) * 8;
        #pragma unroll 8
        for (int k = 0; k < DINv; ++k) {
            unsigned long long w01, x0, x1, x2, x3;
            asm("ld.shared.u64 %0,[%1];" : "=l"(w01) : "r"(wa));
            asm("ld.shared.u64 %0,[%1];" : "=l"(x0) : "r"(xa));
            asm("ld.shared.u64 %0,[%1+8];" : "=l"(x1) : "r"(xa));
            asm("ld.shared.u64 %0,[%1+16];" : "=l"(x2) : "r"(xa));
            asm("ld.shared.u64 %0,[%1+24];" : "=l"(x3) : "r"(xa));
            asm("fma.rn.f32x2 %0,%1,%2,%0;" : "+l"(acc[0]) : "l"(w01), "l"(x0));
            asm("fma.rn.f32x2 %0,%1,%2,%0;" : "+l"(acc[1]) : "l"(w01), "l"(x1));
            asm("fma.rn.f32x2 %0,%1,%2,%0;" : "+l"(acc[2]) : "l"(w01), "l"(x2));
            asm("fma.rn.f32x2 %0,%1,%2,%0;" : "+l"(acc[3]) : "l"(w01), "l"(x3));
            wa += 130 * 4;
            xa += 18 * 8;
        }

        #pragma unroll
        for (int r = 0; r < 4; ++r) {
            float fx, fy;
            asm("mov.b64 {%0,%1},%2;" : "=f"(fx), "=f"(fy) : "l"(acc[r]));
            float2* op = (float2*)&out[(size_t)(R0 + rq * 4 + r) * Hv + jc * 128 + 2 * jp];
            *op = make_float2(fx, fy);
        }
    }
}

// ---------------------------------------------------------------------------
// Phase 2: persistent scan. 256 threads; thread = 8j x 8b block over 16
// strided k. cp.async gather, STS.128 partials, ILP reduce, tanh.approx.
// ---------------------------------------------------------------------------
__global__ void __launch_bounds__(NTHREADS, 1)
esn_scan_kernel(const float* __restrict__ W, float* __restrict__ out)
{
    extern __shared__ unsigned char smem_raw[];
    Smem& sm = *reinterpret_cast<Smem*>(smem_raw);

    const int tid  = threadIdx.x;
    const int lane = tid & 31;
    const int jt   = tid & 3;           // j-octet: j = jt*8 .. jt*8+7
    const int ks   = tid >> 2;          // k-slice 0..63 (k = ks + 64*i)
    const int grp  = blockIdx.x & (NBG - 1);
    const int jg   = blockIdx.x >> 2;
    const int b0   = grp * BTILE;
    const int j0   = jg * JTILE;
    unsigned* bar  = &g_bar[grp * 64];

    const int eb = tid >> 5;            // epilogue batch row 0..7
    const int ej = lane;                // epilogue j within tile

    // one-time W slice: Ws[k*36 + jl] = W[j0+jl][k]
    {
        const int jl = tid & 31;
        for (int k4 = tid >> 5; k4 < Hv / 4; k4 += 8) {
            float4 v = *(const float4*)&W[(size_t)(j0 + jl) * Hv + k4 * 4];
            sm.Ws[(k4 * 4 + 0) * WS + jl] = v.x;
            sm.Ws[(k4 * 4 + 1) * WS + jl] = v.y;
            sm.Ws[(k4 * 4 + 2) * WS + jl] = v.z;
            sm.Ws[(k4 * 4 + 3) * WS + jl] = v.w;
        }
    }

    const unsigned ws_s = (unsigned)__cvta_generic_to_shared(sm.Ws)
                          + (ks * WS + jt * 8) * 4;
    const unsigned hs_s = (unsigned)__cvta_generic_to_shared(sm.u.h_s)
                          + (ks * HS) * 4;
    const unsigned hs_base = (unsigned)__cvta_generic_to_shared(sm.u.h_s);

    __syncthreads();

    const float lr  = 0.9f;
    const float olr = 1.0f - lr;
    float hprev;

    // ---- peeled t = 0: no GEMM ----
    {
        const float u0 = out[((size_t)(b0 + eb) * Tv + 0) * Hv + j0 + ej];
        float th;
        asm("tanh.approx.f32 %0, %1;" : "=f"(th) : "f"(u0));
        const float hnew = lr * th;
        hprev = hnew;
        out[((size_t)(b0 + eb) * Tv + 0) * Hv + j0 + ej] = hnew;
        h_bufT[0][grp][(j0 + ej) * HS + eb] = hnew;
        __syncthreads();
        if (tid == 0)
            asm volatile("red.release.gpu.global.add.u32 [%0], 1;" :: "l"(bar));
    }

    for (int t = 1; t < Tv; ++t) {
        // prefetch u_in (independent of h; consumed after GEMM)
        const float u0 = out[((size_t)(b0 + eb) * Tv + t) * Hv + j0 + ej];

        // group barrier: all 32 CTAs of this batch group finished t-1
        if (tid == 0) {
            const unsigned tgt = (unsigned)t * NJG;
            unsigned v;
            do {
                asm volatile("ld.acquire.gpu.global.u32 %0, [%1];"
                             : "=r"(v) : "l"(bar));
            } while (v < tgt);
        }
        __syncthreads();   // (A) barrier done; prior red reads complete (union)

        // gather: 40KB linear copy via cp.async (no register staging)
        {
            const char* src = (const char*)&h_bufT[(t - 1) & 1][grp][0];
            #pragma unroll
            for (int i = 0; i < 10; ++i) {
                int off = (tid + i * NTHREADS) * 16;
                asm volatile("cp.async.cg.shared.global [%0], [%1], 16;"
                             :: "r"(hs_base + off), "l"(src + off));
            }
            asm volatile("cp.async.commit_group;");
            asm volatile("cp.async.wait_group 0;" ::: "memory");
        }
        __syncthreads();   // (B) h_s ready

        // GEMM: per k = 2 LDS.128 (8 W) + 4 LDS.64 (8 h) + 8 dup + 32 FFMA2
        unsigned long long a[4][8];
        #pragma unroll
        for (int q = 0; q < 4; ++q)
            #pragma unroll
            for (int b = 0; b < 8; ++b) a[q][b] = 0ull;

        {
            unsigned wa = ws_s, ha = hs_s;
            #pragma unroll
            for (int i = 0; i < KPT; ++i) {
                unsigned long long w01, w23, w45, w67;
                float h0, h1, h2, h3, h4, h5, h6, h7;
                asm("ld.shared.v2.u64 {%0,%1},[%2];"
                    : "=l"(w01), "=l"(w23) : "r"(wa));
                asm("ld.shared.v2.u64 {%0,%1},[%2+16];"
                    : "=l"(w45), "=l"(w67) : "r"(wa));
                asm("ld.shared.v2.f32 {%0,%1},[%2];"    : "=f"(h0), "=f"(h1) : "r"(ha));
                asm("ld.shared.v2.f32 {%0,%1},[%2+8];"  : "=f"(h2), "=f"(h3) : "r"(ha));
                asm("ld.shared.v2.f32 {%0,%1},[%2+16];" : "=f"(h4), "=f"(h5) : "r"(ha));
                asm("ld.shared.v2.f32 {%0,%1},[%2+24];" : "=f"(h6), "=f"(h7) : "r"(ha));
                float hv[8] = {h0, h1, h2, h3, h4, h5, h6, h7};
                #pragma unroll
                for (int b = 0; b < 8; ++b) {
                    unsigned long long hd;
                    asm("mov.b64 %0,{%1,%1};" : "=l"(hd) : "f"(hv[b]));
                    asm("fma.rn.f32x2 %0,%1,%2,%0;" : "+l"(a[0][b]) : "l"(w01), "l"(hd));
                    asm("fma.rn.f32x2 %0,%1,%2,%0;" : "+l"(a[1][b]) : "l"(w23), "l"(hd));
                    asm("fma.rn.f32x2 %0,%1,%2,%0;" : "+l"(a[2][b]) : "l"(w45), "l"(hd));
                    asm("fma.rn.f32x2 %0,%1,%2,%0;" : "+l"(a[3][b]) : "l"(w67), "l"(hd));
                }
                wa += 64 * WS * 4;
                ha += 64 * HS * 4;
            }
        }

        __syncthreads();   // (C) h_s reads done before red overwrite (union)

        // k-slice partials: 2 STS.128 per b (thread's 8 j's contiguous)
        #pragma unroll
        for (int b = 0; b < 8; ++b) {
            float x0, y0, x1, y1, x2, y2, x3, y3;
            asm("mov.b64 {%0,%1},%2;" : "=f"(x0), "=f"(y0) : "l"(a[0][b]));
            asm("mov.b64 {%0,%1},%2;" : "=f"(x1), "=f"(y1) : "l"(a[1][b]));
            asm("mov.b64 {%0,%1},%2;" : "=f"(x2), "=f"(y2) : "l"(a[2][b]));
            asm("mov.b64 {%0,%1},%2;" : "=f"(x3), "=f"(y3) : "l"(a[3][b]));
            float* rp = &sm.u.red[ks * RS + b * 36 + jt * 8];
            *(float4*)(rp)     = make_float4(x0, y0, x1, y1);
            *(float4*)(rp + 4) = make_float4(x2, y2, x3, y3);
        }
        __syncthreads();   // (D) red ready

        // reduce 64 k-slices with 4-way ILP (b=eb, j=ej)
        float ssum;
        {
            const float* rp = &sm.u.red[eb * 36 + ej];
            float s0 = 0.f, s1 = 0.f, s2 = 0.f, s3 = 0.f;
            #pragma unroll
            for (int s = 0; s < NKS; s += 4) {
                s0 += rp[(s + 0) * RS];
                s1 += rp[(s + 1) * RS];
                s2 += rp[(s + 2) * RS];
                s3 += rp[(s + 3) * RS];
            }
            ssum = (s0 + s1) + (s2 + s3);
        }

        // epilogue: h_new = 0.1*h + 0.9*tanh(u_in + h@W^T)
        const float u = u0 + ssum;
        float th;
        asm("tanh.approx.f32 %0, %1;" : "=f"(th) : "f"(u));
        const float hnew = olr * hprev + lr * th;
        hprev = hnew;

        {
            float* op = &out[((size_t)(b0 + eb) * Tv + t) * Hv + j0 + ej];
            asm volatile("st.global.cs.f32 [%0], %1;" :: "l"(op), "f"(hnew));
        }
        h_bufT[t & 1][grp][(j0 + ej) * HS + eb] = hnew;

        __syncthreads();   // (E) publish + red reads done
        if (tid == 0)
            asm volatile("red.release.gpu.global.add.u32 [%0], 1;" :: "l"(bar));
    }
}

extern "C" void kernel_launch(void* const* d_in, const int* in_sizes, int n_in,
                              void* d_out, int out_size)
{
    const float* x   = (const float*)d_in[0];  // [32,1000,64]
    const float* Wiw = (const float*)d_in[1];  // [1024,64]
    const float* Wib = (const float*)d_in[2];  // [1024]
    const float* W   = (const float*)d_in[3];  // [1024,1024]
    float* out = (float*)d_out;                // [32,1000,1024]

    const size_t smem = sizeof(Smem);
    cudaFuncSetAttribute(esn_scan_kernel,
                         cudaFuncAttributeMaxDynamicSharedMemorySize, (int)smem);

    esn_uin_kernel<<<(Bv * Tv) / 16, 256>>>(x, Wiw, Wib, out);
    esn_scan_kernel<<<GRID, NTHREADS, smem>>>(W, out);
}